// round 3
// baseline (speedup 1.0000x reference)
#include <cuda_runtime.h>

// ---------------------------------------------------------------------------
// SpookyNetAttention (Performer-style favor+ attention, self-normalized)
//
//   Qp = (exp(Uq - h_q - rowmax(Uq)) + 1e-4)/16        Uq = (Q d^-1/4) @ omega
//   Kp = (exp(Uk - h_k - gmax) + 1e-4)/16              gmax = max over ALL Uk
//   out[n,:] = V[n,:] * (Qp[n]·Kp[n]) / (Qp[n]·S + 1e-8),  S = sum_n Kp[n,:]
//
// 4 launches: init -> kpass -> finalize -> qpass   (all stream-ordered)
// fp32 throughout; GEMMs use packed fma.rn.f32x2 (FFMA2) for 2x fp32 rate.
// ---------------------------------------------------------------------------

#define KD 128          // dim_qk == dim_v
#define MDIM 256        // m (random features)
#define TM 64           // rows per CTA
#define NTHREADS 256
#define N_MAX 262144
#define MAX_NB (N_MAX / TM)

// smem layout (floats): omega[128*256] | A[64*128] | h[64] | red[8*256]
#define SOFF_OM 0
#define SOFF_A  32768
#define SOFF_H  (32768 + 8192)
#define SOFF_RED (SOFF_H + 64)
#define SMEM_FLOATS (SOFF_RED + 2048)
#define SMEM_BYTES (SMEM_FLOATS * 4)

// scratch (device globals: allocation-free per harness rules)
__device__ float    g_UKmh[(size_t)N_MAX * MDIM];   // U_K - h_K   (256 MiB)
__device__ float    g_Spart[MAX_NB * MDIM];         // per-block colsum partials
__device__ float    g_S[MDIM];                      // final sum(Kp, axis=0)
__device__ unsigned g_gmax_enc;                     // monotonic-uint encoded max
__device__ float    g_gmax;

// ---------------- helpers ----------------
__device__ __forceinline__ unsigned enc_f(float f) {
    unsigned u = __float_as_uint(f);
    return (u & 0x80000000u) ? ~u : (u | 0x80000000u);
}
__device__ __forceinline__ float dec_f(unsigned u) {
    u = (u & 0x80000000u) ? (u & 0x7FFFFFFFu) : ~u;
    return __uint_as_float(u);
}
__device__ __forceinline__ void fma2(unsigned long long& d,
                                     unsigned long long a, unsigned long long b) {
    asm("fma.rn.f32x2 %0, %1, %2, %0;" : "+l"(d) : "l"(a), "l"(b));
}
__device__ __forceinline__ unsigned long long pack2(float lo, float hi) {
    unsigned long long r;
    asm("mov.b64 %0, {%1, %2};" : "=l"(r) : "f"(lo), "f"(hi));
    return r;
}
__device__ __forceinline__ void unpack2(unsigned long long v, float& lo, float& hi) {
    asm("mov.b64 {%0, %1}, %2;" : "=f"(lo), "=f"(hi) : "l"(v));
}

// Load omega (full 128x256) + scaled X tile (64x128, row-major) + per-row h.
// Warp w owns rows {w, w+8, ..., w+56} for the load/h phase (shfl-reduced h).
__device__ __forceinline__ void load_tiles(const float* __restrict__ X,
                                           const float* __restrict__ omega,
                                           float* s_om, float* s_A, float* s_h,
                                           int base, int tid) {
    #pragma unroll
    for (int i = 0; i < 32; ++i) {
        int idx = tid * 4 + i * 1024;
        *(float4*)(s_om + idx) = *(const float4*)(omega + idx);
    }
    const float sc = 0.29730177875068026f;  // 128^-0.25
    int w = tid >> 5, lane = tid & 31;
    #pragma unroll
    for (int it = 0; it < 8; ++it) {
        int r = w + it * 8;
        float4 x = *(const float4*)(X + (size_t)(base + r) * KD + lane * 4);
        x.x *= sc; x.y *= sc; x.z *= sc; x.w *= sc;
        *(float4*)(s_A + r * KD + lane * 4) = x;
        float ss = x.x * x.x + x.y * x.y + x.z * x.z + x.w * x.w;
        #pragma unroll
        for (int o = 16; o; o >>= 1) ss += __shfl_xor_sync(0xffffffffu, ss, o);
        if (lane == 0) s_h[r] = 0.5f * ss;  // h = 0.5 * sum((x*d^-1/4)^2)
    }
}

// C[64x256] = A[64x128] @ omega[128x256], per-thread 8 rows x 8 cols (4 f32x2 pairs)
__device__ __forceinline__ void gemm_tile(const float* s_om, const float* s_A,
                                          int row0, int colb,
                                          unsigned long long acc[8][4]) {
    #pragma unroll 2
    for (int k0 = 0; k0 < KD; k0 += 4) {
        float av[8][4];
        #pragma unroll
        for (int i = 0; i < 8; ++i) {
            float4 t = *(const float4*)(s_A + (row0 + i) * KD + k0);  // broadcast
            av[i][0] = t.x; av[i][1] = t.y; av[i][2] = t.z; av[i][3] = t.w;
        }
        #pragma unroll
        for (int kk = 0; kk < 4; ++kk) {
            ulonglong2 b01 = *(const ulonglong2*)(s_om + (k0 + kk) * MDIM + colb);
            ulonglong2 b23 = *(const ulonglong2*)(s_om + (k0 + kk) * MDIM + colb + 4);
            #pragma unroll
            for (int i = 0; i < 8; ++i) {
                unsigned long long a2 = pack2(av[i][kk], av[i][kk]);
                fma2(acc[i][0], a2, b01.x);
                fma2(acc[i][1], a2, b01.y);
                fma2(acc[i][2], a2, b23.x);
                fma2(acc[i][3], a2, b23.y);
            }
        }
    }
}

// ---------------- kernels ----------------
extern "C" __global__ void spooky_init() {
    if (threadIdx.x == 0) g_gmax_enc = 0u;  // decodes below any finite float
}

extern "C" __global__ void __launch_bounds__(NTHREADS, 1)
spooky_kpass(const float* __restrict__ Kin, const float* __restrict__ omega) {
    extern __shared__ float smem[];
    float* s_om = smem + SOFF_OM;
    float* s_A  = smem + SOFF_A;
    float* s_h  = smem + SOFF_H;
    float* s_red = smem + SOFF_RED;
    const int tid = threadIdx.x;
    const int base = blockIdx.x * TM;

    load_tiles(Kin, omega, s_om, s_A, s_h, base, tid);
    __syncthreads();

    unsigned long long acc[8][4];
    #pragma unroll
    for (int i = 0; i < 8; ++i)
        #pragma unroll
        for (int j = 0; j < 4; ++j) acc[i][j] = 0ULL;

    const int row0 = (tid >> 5) * 8;
    const int colb = (tid & 31) * 8;
    gemm_tile(s_om, s_A, row0, colb, acc);

    // unpack U
    float u[8][8];
    #pragma unroll
    for (int i = 0; i < 8; ++i)
        #pragma unroll
        for (int jp = 0; jp < 4; ++jp)
            unpack2(acc[i][jp], u[i][2 * jp], u[i][2 * jp + 1]);

    // global max of U (pre h-subtraction, matching jnp.max(U))
    float tmax = -3.402823466e38f;
    #pragma unroll
    for (int i = 0; i < 8; ++i)
        #pragma unroll
        for (int j = 0; j < 8; ++j) tmax = fmaxf(tmax, u[i][j]);
    #pragma unroll
    for (int o = 16; o; o >>= 1)
        tmax = fmaxf(tmax, __shfl_xor_sync(0xffffffffu, tmax, o));
    if ((tid & 31) == 0) atomicMax(&g_gmax_enc, enc_f(tmax));

    // store U-h, accumulate per-column partial sums of exp(U-h)
    float cs[8];
    #pragma unroll
    for (int j = 0; j < 8; ++j) cs[j] = 0.f;
    #pragma unroll
    for (int i = 0; i < 8; ++i) {
        int r = row0 + i;
        float h = s_h[r];
        float um[8];
        #pragma unroll
        for (int j = 0; j < 8; ++j) {
            um[j] = u[i][j] - h;
            cs[j] += __expf(um[j]);     // <= exp(gmax) ~ 5e8, safe in fp32
        }
        size_t off = (size_t)(base + r) * MDIM + colb;
        float4 st0 = make_float4(um[0], um[1], um[2], um[3]);
        float4 st1 = make_float4(um[4], um[5], um[6], um[7]);
        *(float4*)(g_UKmh + off) = st0;
        *(float4*)(g_UKmh + off + 4) = st1;
    }
    #pragma unroll
    for (int j = 0; j < 8; ++j) s_red[(tid >> 5) * MDIM + colb + j] = cs[j];
    __syncthreads();
    float v = 0.f;
    #pragma unroll
    for (int w2 = 0; w2 < 8; ++w2) v += s_red[w2 * MDIM + tid];
    g_Spart[blockIdx.x * MDIM + tid] = v;   // deterministic partial, no atomics
}

// one block per column j: reduce partials, fold in gmax + eps terms
extern "C" __global__ void spooky_finalize(int nb, int n) {
    __shared__ float red[256];
    const int j = blockIdx.x, tid = threadIdx.x;
    float a = 0.f;
    for (int r = tid; r < nb; r += 256) a += g_Spart[r * MDIM + j];
    red[tid] = a;
    __syncthreads();
    for (int s = 128; s; s >>= 1) {
        if (tid < s) red[tid] += red[tid + s];
        __syncthreads();
    }
    if (tid == 0) {
        float gmax = dec_f(g_gmax_enc);
        // S[j] = (e^-gmax * sum exp(U-h) + n*1e-4) / sqrt(m)
        g_S[j] = (__expf(-gmax) * red[0] + (float)n * 1e-4f) * 0.0625f;
        if (j == 0) g_gmax = gmax;
    }
}

extern "C" __global__ void __launch_bounds__(NTHREADS, 1)
spooky_qpass(const float* __restrict__ Q, const float* __restrict__ V,
             const float* __restrict__ omega, float* __restrict__ out) {
    extern __shared__ float smem[];
    float* s_om = smem + SOFF_OM;
    float* s_A  = smem + SOFF_A;
    float* s_h  = smem + SOFF_H;
    float* s_S  = smem + SOFF_RED;          // 256 floats
    float* s_scale = smem + SOFF_RED + 256; // 64 floats
    const int tid = threadIdx.x;
    const int base = blockIdx.x * TM;

    s_S[tid] = g_S[tid];
    load_tiles(Q, omega, s_om, s_A, s_h, base, tid);
    __syncthreads();

    unsigned long long acc[8][4];
    #pragma unroll
    for (int i = 0; i < 8; ++i)
        #pragma unroll
        for (int j = 0; j < 4; ++j) acc[i][j] = 0ULL;

    const int row0 = (tid >> 5) * 8;
    const int colb = (tid & 31) * 8;
    gemm_tile(s_om, s_A, row0, colb, acc);

    const float gmax = g_gmax;
    const int lane = tid & 31;

    float u[8][8];
    #pragma unroll
    for (int i = 0; i < 8; ++i)
        #pragma unroll
        for (int jp = 0; jp < 4; ++jp)
            unpack2(acc[i][jp], u[i][2 * jp], u[i][2 * jp + 1]);

    #pragma unroll
    for (int i = 0; i < 8; ++i) {
        const int r = row0 + i;
        // per-row max of Uq across all 256 cols (row lives in one warp)
        float rm = u[i][0];
        #pragma unroll
        for (int j = 1; j < 8; ++j) rm = fmaxf(rm, u[i][j]);
        #pragma unroll
        for (int o = 16; o; o >>= 1)
            rm = fmaxf(rm, __shfl_xor_sync(0xffffffffu, rm, o));

        const float hb = s_h[r] + rm;
        size_t off = (size_t)(base + r) * MDIM + colb;
        float4 k0v = *(const float4*)(g_UKmh + off);
        float4 k1v = *(const float4*)(g_UKmh + off + 4);
        float km[8] = {k0v.x, k0v.y, k0v.z, k0v.w, k1v.x, k1v.y, k1v.z, k1v.w};

        float wa = 0.f, na = 0.f;
        #pragma unroll
        for (int j = 0; j < 8; ++j) {
            float qp = __expf(u[i][j] - hb) + 1e-4f;   // = 16*Qp
            float kp = __expf(km[j] - gmax) + 1e-4f;   // = 16*Kp
            wa += qp * kp;
            na += qp * s_S[colb + j];
        }
        #pragma unroll
        for (int o = 16; o; o >>= 1) {
            wa += __shfl_xor_sync(0xffffffffu, wa, o);
            na += __shfl_xor_sync(0xffffffffu, na, o);
        }
        if (lane == 0)
            s_scale[r] = (wa * (1.f / 256.f)) / (na * (1.f / 16.f) + 1e-8f);
    }
    __syncthreads();

    // out[n,:] = V[n,:] * scale[n]
    const int w = tid >> 5;
    #pragma unroll
    for (int it = 0; it < 8; ++it) {
        int r = w + it * 8;
        float sc = s_scale[r];
        size_t o4 = (size_t)(base + r) * KD + lane * 4;
        float4 v = *(const float4*)(V + o4);
        v.x *= sc; v.y *= sc; v.z *= sc; v.w *= sc;
        *(float4*)(out + o4) = v;
    }
}

// ---------------- launcher ----------------
extern "C" void kernel_launch(void* const* d_in, const int* in_sizes, int n_in,
                              void* d_out, int out_size) {
    const float* Q     = (const float*)d_in[0];
    const float* K     = (const float*)d_in[1];
    const float* V     = (const float*)d_in[2];
    const float* omega = (const float*)d_in[3];
    const int n  = in_sizes[0] / KD;
    const int nb = n / TM;

    cudaFuncSetAttribute(spooky_kpass, cudaFuncAttributeMaxDynamicSharedMemorySize, SMEM_BYTES);
    cudaFuncSetAttribute(spooky_qpass, cudaFuncAttributeMaxDynamicSharedMemorySize, SMEM_BYTES);

    spooky_init<<<1, 32>>>();
    spooky_kpass<<<nb, NTHREADS, SMEM_BYTES>>>(K, omega);
    spooky_finalize<<<MDIM, 256>>>(nb, n);
    spooky_qpass<<<nb, NTHREADS, SMEM_BYTES>>>(Q, V, omega, (float*)d_out);
}

// round 7
// speedup vs baseline: 1.8546x; 1.8546x over previous
#include <cuda_runtime.h>
#include <cuda_bf16.h>
#include <cstdint>

// ---------------------------------------------------------------------------
// SpookyNetAttention — split-bf16 (hi/lo, 3-product) GEMM on mma.sync HMMA.
// (tcgen05 is unavailable: harness builds via compute_103 virtual arch.)
//
//   U = X @ (sc*omega),  sc = d^-1/4 folded into B = omega^T.
//   U ≈ Ah@Bh + Ah@Bl + Al@Bh  (bf16 mma.sync, fp32 accum; dropped Al@Bl
//   term is ~2^-18 relative).
//
//   kpass: U_K -> store exp(Uk-h) column-major scratch, colsum partials,
//          global max(Uk) via encoded atomicMax
//   fin:   reduce partials -> S[j] = (e^-gmax * sum + N*1e-4)/16, decode gmax
//   qpass: U_Q -> rowmax, Qp, reload scratch, w/norm, out = V * w/norm
// ---------------------------------------------------------------------------

#define KD   128
#define MD   256
#define TM   128            // rows per CTA
#define NTH  512            // 16 warps, 4 row-warps x 4 col-warps
#define N_MAX 262144
#define MAX_NB (N_MAX / TM)

#define SP   136            // padded smem row stride (bf16 elems) -> conflict-free frags

// smem byte offsets
#define SO_BH   0                       // [256][136] bf16  (69632 B)
#define SO_BL   69632
#define SO_AH   139264                  // [128][136] bf16  (34816 B)
#define SO_AL   174080
#define SO_H    208896                  // 128 floats
#define SO_S    209408                  // 256 floats
#define SO_RED  210432                  // 3 x 2KB reduction buffers (6144 B)
#define SO_SC   216576                  // 128 floats
#define SMEM_BYTES 217088

// device scratch (allocation-free per harness rules)
__device__ __nv_bfloat16 g_BT_hi[MD * KD];      // (sc*omega)^T, [n][k]
__device__ __nv_bfloat16 g_BT_lo[MD * KD];
__device__ float    g_UKe[(size_t)N_MAX * MD];  // exp(Uk-h), COLUMN-major [col][row]
__device__ float    g_Spart[MAX_NB * MD];       // per-CTA colsum partials
__device__ float    g_S[MD];
__device__ unsigned g_gmax_enc;
__device__ float    g_gmax;

// ---------------- helpers ----------------
__device__ __forceinline__ unsigned enc_f(float f) {
    unsigned u = __float_as_uint(f);
    return (u & 0x80000000u) ? ~u : (u | 0x80000000u);
}
__device__ __forceinline__ float dec_f(unsigned u) {
    u = (u & 0x80000000u) ? (u & 0x7FFFFFFFu) : ~u;
    return __uint_as_float(u);
}

__device__ __forceinline__ void mma16816(float c[4], const uint32_t a[4],
                                         uint32_t b0, uint32_t b1) {
    asm volatile(
        "mma.sync.aligned.m16n8k16.row.col.f32.bf16.bf16.f32 "
        "{%0,%1,%2,%3}, {%4,%5,%6,%7}, {%8,%9}, {%0,%1,%2,%3};"
        : "+f"(c[0]), "+f"(c[1]), "+f"(c[2]), "+f"(c[3])
        : "r"(a[0]), "r"(a[1]), "r"(a[2]), "r"(a[3]), "r"(b0), "r"(b1));
}

// ---------------- shared device functions ----------------

// B (omega^T hi/lo, [256][128] bf16 dense in gmem) -> padded smem. 512 thr.
__device__ __forceinline__ void load_B(char* sm, int tid) {
    #pragma unroll
    for (int it = 0; it < 16; ++it) {
        int c = tid + it * NTH;             // 8B chunk id, 0..8191
        int row = c >> 5;
        int pos = (c & 31) * 4;
        uint2 vh = *(const uint2*)((const char*)g_BT_hi + (row * KD + pos) * 2);
        uint2 vl = *(const uint2*)((const char*)g_BT_lo + (row * KD + pos) * 2);
        *(uint2*)(sm + SO_BH + (row * SP + pos) * 2) = vh;
        *(uint2*)(sm + SO_BL + (row * SP + pos) * 2) = vl;
    }
}

// A tile: 128 rows fp32 -> bf16 hi/lo padded smem + per-row h.
__device__ __forceinline__ void load_A(const float* __restrict__ X, int base,
                                       char* sm, float* s_h, int tid) {
    const int lane = tid & 31;
    #pragma unroll
    for (int it = 0; it < 8; ++it) {
        int c = tid + it * NTH;             // float4 chunk id, 0..4095
        int row = c >> 5;                   // one full row per (warp, it)
        int pos = (c & 31) * 4;
        float4 x = *(const float4*)(X + (size_t)(base + row) * KD + pos);
        float ss = x.x * x.x + x.y * x.y + x.z * x.z + x.w * x.w;
        #pragma unroll
        for (int o = 16; o; o >>= 1) ss += __shfl_xor_sync(0xffffffffu, ss, o);
        if (lane == 0) s_h[row] = ss * 0.04419417382415922f;  // 1/(2*sqrt(128))

        __nv_bfloat16 h0 = __float2bfloat16(x.x), h1 = __float2bfloat16(x.y);
        __nv_bfloat16 h2 = __float2bfloat16(x.z), h3 = __float2bfloat16(x.w);
        __nv_bfloat16 l0 = __float2bfloat16(x.x - __bfloat162float(h0));
        __nv_bfloat16 l1 = __float2bfloat16(x.y - __bfloat162float(h1));
        __nv_bfloat16 l2 = __float2bfloat16(x.z - __bfloat162float(h2));
        __nv_bfloat16 l3 = __float2bfloat16(x.w - __bfloat162float(h3));
        __nv_bfloat162* ph = (__nv_bfloat162*)(sm + SO_AH + (row * SP + pos) * 2);
        __nv_bfloat162* pl = (__nv_bfloat162*)(sm + SO_AL + (row * SP + pos) * 2);
        ph[0] = __nv_bfloat162(h0, h1); ph[1] = __nv_bfloat162(h2, h3);
        pl[0] = __nv_bfloat162(l0, l1); pl[1] = __nv_bfloat162(l2, l3);
    }
}

// Warp GEMM: 32x64 tile at (rb, cb); c[mf][nf][4] fp32 accumulators.
// c element (mf,nf,e): row = rb+mf*16+lq+(e&2?8:0), col = cb+nf*8+lr*2+(e&1).
__device__ __forceinline__ void gemm_warp(const char* sm, int rb, int cb,
                                          int lq, int lr, float c[2][8][4]) {
    #pragma unroll
    for (int mf = 0; mf < 2; ++mf)
        #pragma unroll
        for (int nf = 0; nf < 8; ++nf)
            #pragma unroll
            for (int e = 0; e < 4; ++e) c[mf][nf][e] = 0.f;

    #pragma unroll 1
    for (int k0 = 0; k0 < KD; k0 += 16) {
        uint32_t ah[2][4], al[2][4];
        #pragma unroll
        for (int mf = 0; mf < 2; ++mf) {
            int off = ((rb + mf * 16 + lq) * SP + k0 + lr * 2) * 2;
            ah[mf][0] = *(const uint32_t*)(sm + SO_AH + off);
            ah[mf][1] = *(const uint32_t*)(sm + SO_AH + off + 8 * SP * 2);
            ah[mf][2] = *(const uint32_t*)(sm + SO_AH + off + 16);
            ah[mf][3] = *(const uint32_t*)(sm + SO_AH + off + 8 * SP * 2 + 16);
            al[mf][0] = *(const uint32_t*)(sm + SO_AL + off);
            al[mf][1] = *(const uint32_t*)(sm + SO_AL + off + 8 * SP * 2);
            al[mf][2] = *(const uint32_t*)(sm + SO_AL + off + 16);
            al[mf][3] = *(const uint32_t*)(sm + SO_AL + off + 8 * SP * 2 + 16);
        }
        #pragma unroll
        for (int nf = 0; nf < 8; ++nf) {
            int boff = ((cb + nf * 8 + lq) * SP + k0 + lr * 2) * 2;
            uint32_t bh0 = *(const uint32_t*)(sm + SO_BH + boff);
            uint32_t bh1 = *(const uint32_t*)(sm + SO_BH + boff + 16);
            uint32_t bl0 = *(const uint32_t*)(sm + SO_BL + boff);
            uint32_t bl1 = *(const uint32_t*)(sm + SO_BL + boff + 16);
            #pragma unroll
            for (int mf = 0; mf < 2; ++mf) {
                mma16816(c[mf][nf], ah[mf], bh0, bh1);
                mma16816(c[mf][nf], ah[mf], bl0, bl1);
                mma16816(c[mf][nf], al[mf], bh0, bh1);
            }
        }
    }
}

// ---------------- kernels ----------------
extern "C" __global__ void spooky_prep(const float* __restrict__ omega) {
    int n = blockIdx.x, k = threadIdx.x;
    float v = omega[k * MD + n] * 0.29730177875068026f;   // fold d^-1/4 into B
    __nv_bfloat16 hi = __float2bfloat16(v);
    __nv_bfloat16 lo = __float2bfloat16(v - __bfloat162float(hi));
    g_BT_hi[n * KD + k] = hi;
    g_BT_lo[n * KD + k] = lo;
    if (n == 0 && k == 0) g_gmax_enc = 0u;
}

extern "C" __global__ void __launch_bounds__(NTH, 1)
spooky_kpass(const float* __restrict__ Kin, int ntot) {
    extern __shared__ __align__(16) char sm[];
    float* s_h  = (float*)(sm + SO_H);
    float* redC = (float*)(sm + SO_RED);     // [col][wr] colsum partials (4KB)
    const int tid = threadIdx.x, wid = tid >> 5, lane = tid & 31;
    const int lq = lane >> 2, lr = lane & 3;
    const int wr = wid & 3, wc = wid >> 2;
    const int rb = wr * 32, cb = wc * 64;
    const int base = blockIdx.x * TM;

    load_B(sm, tid);
    load_A(Kin, base, sm, s_h, tid);
    __syncthreads();

    float c[2][8][4];
    gemm_warp(sm, rb, cb, lq, lr, c);

    // h for this thread's 4 row slots
    float h4[4];
    #pragma unroll
    for (int s = 0; s < 4; ++s) h4[s] = s_h[rb + (s >> 1) * 16 + lq + (s & 1) * 8];

    // global max(U), exp(U-h) -> column-major scratch, colsum partials
    float umax = -3.402823466e38f;
    float cs[16];
    #pragma unroll
    for (int j = 0; j < 16; ++j) cs[j] = 0.f;

    #pragma unroll
    for (int mf = 0; mf < 2; ++mf)
        #pragma unroll
        for (int nf = 0; nf < 8; ++nf)
            #pragma unroll
            for (int e = 0; e < 4; ++e) {
                float u = c[mf][nf][e];
                umax = fmaxf(umax, u);
                int rloc = rb + mf * 16 + lq + ((e & 2) ? 8 : 0);
                int col  = cb + nf * 8 + lr * 2 + (e & 1);
                float v = __expf(u - h4[mf * 2 + ((e >> 1) & 1)]);
                g_UKe[(size_t)col * ntot + (base + rloc)] = v;
                cs[nf * 2 + (e & 1)] += v;
            }

    #pragma unroll
    for (int o = 16; o; o >>= 1)
        umax = fmaxf(umax, __shfl_xor_sync(0xffffffffu, umax, o));
    if (lane == 0) atomicMax(&g_gmax_enc, enc_f(umax));

    // reduce colsums over lq (lanes xor 4,8,16); lanes lq==0 hold col totals
    #pragma unroll
    for (int j = 0; j < 16; ++j) {
        float v = cs[j];
        v += __shfl_xor_sync(0xffffffffu, v, 4);
        v += __shfl_xor_sync(0xffffffffu, v, 8);
        v += __shfl_xor_sync(0xffffffffu, v, 16);
        cs[j] = v;
    }
    if (lq == 0) {
        #pragma unroll
        for (int nf = 0; nf < 8; ++nf)
            #pragma unroll
            for (int e1 = 0; e1 < 2; ++e1)
                redC[(cb + nf * 8 + lr * 2 + e1) * 4 + wr] = cs[nf * 2 + e1];
    }
    __syncthreads();
    if (tid < MD) {
        float v = redC[tid * 4] + redC[tid * 4 + 1] + redC[tid * 4 + 2] + redC[tid * 4 + 3];
        g_Spart[blockIdx.x * MD + tid] = v;
    }
}

// one block per column j
extern "C" __global__ void spooky_fin(int nb, int ntot) {
    __shared__ float red[256];
    const int j = blockIdx.x, tid = threadIdx.x;
    float a = 0.f;
    for (int r = tid; r < nb; r += 256) a += g_Spart[r * MD + j];
    red[tid] = a;
    __syncthreads();
    for (int s = 128; s; s >>= 1) {
        if (tid < s) red[tid] += red[tid + s];
        __syncthreads();
    }
    if (tid == 0) {
        float g = dec_f(g_gmax_enc);
        g_S[j] = (__expf(-g) * red[0] + (float)ntot * 1e-4f) * 0.0625f;
        if (j == 0) g_gmax = g;
    }
}

extern "C" __global__ void __launch_bounds__(NTH, 1)
spooky_qpass(const float* __restrict__ Q, const float* __restrict__ V,
             float* __restrict__ out, int ntot) {
    extern __shared__ __align__(16) char sm[];
    float* s_h  = (float*)(sm + SO_H);
    float* s_S  = (float*)(sm + SO_S);
    float* redM = (float*)(sm + SO_RED);          // rowmax  [row][wc] 2KB
    float* redW = (float*)(sm + SO_RED + 2048);   // w part
    float* redN = (float*)(sm + SO_RED + 4096);   // norm part
    float* s_sc = (float*)(sm + SO_SC);
    const int tid = threadIdx.x, wid = tid >> 5, lane = tid & 31;
    const int lq = lane >> 2, lr = lane & 3;
    const int wr = wid & 3, wc = wid >> 2;
    const int rb = wr * 32, cb = wc * 64;
    const int base = blockIdx.x * TM;

    if (tid < MD) s_S[tid] = g_S[tid];
    load_B(sm, tid);
    load_A(Q, base, sm, s_h, tid);
    __syncthreads();

    float c[2][8][4];
    gemm_warp(sm, rb, cb, lq, lr, c);

    // round 1: per-row max over this warp's 64 cols, then cross-warp via smem
    #pragma unroll
    for (int s = 0; s < 4; ++s) {
        int mf = s >> 1, hi = s & 1;
        float m = c[mf][0][hi * 2];
        #pragma unroll
        for (int nf = 0; nf < 8; ++nf) {
            m = fmaxf(m, c[mf][nf][hi * 2]);
            m = fmaxf(m, c[mf][nf][hi * 2 + 1]);
        }
        m = fmaxf(m, __shfl_xor_sync(0xffffffffu, m, 1));
        m = fmaxf(m, __shfl_xor_sync(0xffffffffu, m, 2));
        if (lr == 0) redM[(rb + mf * 16 + lq + hi * 8) * 4 + wc] = m;
    }
    __syncthreads();

    const float expg = __expf(-g_gmax);

    // round 2: qp = exp(u - h - rowmax), kp from scratch, w & norm partials
    float wa4[4], na4[4];
    #pragma unroll
    for (int s = 0; s < 4; ++s) {
        int mf = s >> 1, hi = s & 1;
        int rloc = rb + mf * 16 + lq + hi * 8;
        float rm = fmaxf(fmaxf(redM[rloc * 4], redM[rloc * 4 + 1]),
                         fmaxf(redM[rloc * 4 + 2], redM[rloc * 4 + 3]));
        float hb = s_h[rloc] + rm;
        int rowg = base + rloc;
        float wa = 0.f, na = 0.f;
        #pragma unroll
        for (int nf = 0; nf < 8; ++nf)
            #pragma unroll
            for (int e1 = 0; e1 < 2; ++e1) {
                int col = cb + nf * 8 + lr * 2 + e1;
                float qp = __expf(c[mf][nf][hi * 2 + e1] - hb) + 1e-4f;  // 16*Qp
                float kp = g_UKe[(size_t)col * ntot + rowg] * expg + 1e-4f; // 16*Kp
                wa += qp * kp;
                na += qp * s_S[col];
            }
        wa += __shfl_xor_sync(0xffffffffu, wa, 1);
        wa += __shfl_xor_sync(0xffffffffu, wa, 2);
        na += __shfl_xor_sync(0xffffffffu, na, 1);
        na += __shfl_xor_sync(0xffffffffu, na, 2);
        wa4[s] = wa; na4[s] = na;
    }
    #pragma unroll
    for (int s = 0; s < 4; ++s) {
        int mf = s >> 1, hi = s & 1;
        int rloc = rb + mf * 16 + lq + hi * 8;
        if (lr == 0) { redW[rloc * 4 + wc] = wa4[s]; redN[rloc * 4 + wc] = na4[s]; }
    }
    __syncthreads();

    if (tid < TM) {
        float w = redW[tid * 4] + redW[tid * 4 + 1] + redW[tid * 4 + 2] + redW[tid * 4 + 3];
        float n = redN[tid * 4] + redN[tid * 4 + 1] + redN[tid * 4 + 2] + redN[tid * 4 + 3];
        s_sc[tid] = (w * (1.f / 256.f)) / (n * (1.f / 16.f) + 1e-8f);
    }
    __syncthreads();

    // out[n,:] = V[n,:] * scale[n]   (warp per row, lane per float4)
    #pragma unroll
    for (int it = 0; it < 8; ++it) {
        int r = wid * 8 + it;
        float sc = s_sc[r];
        size_t o = (size_t)(base + r) * KD + lane * 4;
        float4 v = *(const float4*)(V + o);
        v.x *= sc; v.y *= sc; v.z *= sc; v.w *= sc;
        *(float4*)(out + o) = v;
    }
}

// ---------------- launcher ----------------
extern "C" void kernel_launch(void* const* d_in, const int* in_sizes, int n_in,
                              void* d_out, int out_size) {
    const float* Q     = (const float*)d_in[0];
    const float* K     = (const float*)d_in[1];
    const float* V     = (const float*)d_in[2];
    const float* omega = (const float*)d_in[3];
    const int n  = in_sizes[0] / KD;
    const int nb = n / TM;

    cudaFuncSetAttribute(spooky_kpass, cudaFuncAttributeMaxDynamicSharedMemorySize, SMEM_BYTES);
    cudaFuncSetAttribute(spooky_qpass, cudaFuncAttributeMaxDynamicSharedMemorySize, SMEM_BYTES);

    spooky_prep<<<MD, KD>>>(omega);
    spooky_kpass<<<nb, NTH, SMEM_BYTES>>>(K, n);
    spooky_fin<<<MD, 256>>>(nb, n);
    spooky_qpass<<<nb, NTH, SMEM_BYTES>>>(Q, V, (float*)d_out, n);
}

// round 9
// speedup vs baseline: 2.1784x; 1.1746x over previous
#include <cuda_runtime.h>
#include <cuda_bf16.h>
#include <cuda_fp16.h>
#include <cstdint>

// ---------------------------------------------------------------------------
// SpookyNetAttention — split-bf16 (hi/lo, 3-product) GEMM on mma.sync,
// ldmatrix fragments, fp16 scratch with per-tile max scaling, persistent
// CTAs with atomic work queue + A-tile prefetch overlap.
//
//   kpass: U_K -> store exp(Uk-h-bmax) (half) col-major, colsum partials,
//          per-tile bmax, global gmax via encoded atomicMax
//   fin:   S[j] = (sum_t e^{bmax_t-gmax}*Spart[t][j] + N*1e-4)/16
//   qpass: U_Q -> rowmax, Qp, reload scratch (*e^{bmax-gmax}), w/norm,
//          out = V * w/norm
// ---------------------------------------------------------------------------

#define KD   128
#define MD   256
#define TM   128
#define NTH  512            // 16 warps, 4x4 warp grid, warp tile 32x64
#define N_MAX 262144
#define MAX_NB (N_MAX / TM)
#define SP   136            // padded bf16 row stride; word stride 68 = 4 mod 32
#define PGRID 192           // persistent CTAs (>= SM count; extras exit fast)

// smem byte offsets
#define SO_BH   0                       // [256][136] bf16
#define SO_BL   69632
#define SO_AH   139264                  // [128][136] bf16
#define SO_AL   174080
#define SO_H    208896                  // 128 floats
#define SO_S    209408                  // 256 floats
#define SO_RED  210432                  // 3 x 2KB reduction buffers
#define SO_SC   216576                  // 128 floats
#define SO_RR   217088                  // 16 floats (warp maxes)
#define SO_CT   217152                  // next-tile broadcast (int)
#define SMEM_BYTES 217216

#define DAL (SO_AL - SO_AH)
#define DBL (SO_BL - SO_BH)

// device scratch (allocation-free per harness rules)
__device__ __nv_bfloat16 g_BT_hi[MD * KD];
__device__ __nv_bfloat16 g_BT_lo[MD * KD];
__device__ __half   g_UKh[(size_t)N_MAX * MD];  // exp(Uk-h-bmax), col-major
__device__ float    g_Spart[MAX_NB * MD];
__device__ float    g_bmax[MAX_NB];
__device__ float    g_S[MD];
__device__ unsigned g_gmax_enc;
__device__ float    g_gmax;
__device__ int      g_ctrK, g_ctrQ;

// ---------------- helpers ----------------
__device__ __forceinline__ unsigned enc_f(float f) {
    unsigned u = __float_as_uint(f);
    return (u & 0x80000000u) ? ~u : (u | 0x80000000u);
}
__device__ __forceinline__ float dec_f(unsigned u) {
    u = (u & 0x80000000u) ? (u & 0x7FFFFFFFu) : ~u;
    return __uint_as_float(u);
}
__device__ __forceinline__ uint32_t smem_u32(const void* p) {
    uint32_t a;
    asm("{ .reg .u64 t; cvta.to.shared.u64 t, %1; cvt.u32.u64 %0, t; }" : "=r"(a) : "l"(p));
    return a;
}
__device__ __forceinline__ void mma16816(float c[4], const uint32_t a[4],
                                         uint32_t b0, uint32_t b1) {
    asm volatile(
        "mma.sync.aligned.m16n8k16.row.col.f32.bf16.bf16.f32 "
        "{%0,%1,%2,%3}, {%4,%5,%6,%7}, {%8,%9}, {%0,%1,%2,%3};"
        : "+f"(c[0]), "+f"(c[1]), "+f"(c[2]), "+f"(c[3])
        : "r"(a[0]), "r"(a[1]), "r"(a[2]), "r"(a[3]), "r"(b0), "r"(b1));
}
#define LDSM4(R, A)                                                         \
    asm volatile("ldmatrix.sync.aligned.m8n8.x4.shared.b16 {%0,%1,%2,%3}, [%4];" \
        : "=r"((R)[0]), "=r"((R)[1]), "=r"((R)[2]), "=r"((R)[3]) : "r"(A))

// ---------------- shared device functions ----------------

// B (omega^T hi/lo) -> padded smem. 512 threads, once per CTA.
__device__ __forceinline__ void load_B(char* sm, int tid) {
    #pragma unroll
    for (int it = 0; it < 16; ++it) {
        int c = tid + it * NTH;
        int row = c >> 5;
        int pos = (c & 31) * 4;
        uint2 vh = *(const uint2*)((const char*)g_BT_hi + (row * KD + pos) * 2);
        uint2 vl = *(const uint2*)((const char*)g_BT_lo + (row * KD + pos) * 2);
        *(uint2*)(sm + SO_BH + (row * SP + pos) * 2) = vh;
        *(uint2*)(sm + SO_BL + (row * SP + pos) * 2) = vl;
    }
}

// A tile: 128 rows fp32 -> bf16 hi/lo padded smem + per-row h.
__device__ __forceinline__ void load_A(const float* __restrict__ X, int base,
                                       char* sm, float* s_h, int tid) {
    const int lane = tid & 31;
    #pragma unroll
    for (int it = 0; it < 8; ++it) {
        int c = tid + it * NTH;
        int row = c >> 5;
        int pos = (c & 31) * 4;
        float4 x = *(const float4*)(X + (size_t)(base + row) * KD + pos);
        float ss = x.x * x.x + x.y * x.y + x.z * x.z + x.w * x.w;
        #pragma unroll
        for (int o = 16; o; o >>= 1) ss += __shfl_xor_sync(0xffffffffu, ss, o);
        if (lane == 0) s_h[row] = ss * 0.04419417382415922f;  // 1/(2*sqrt(128))

        __nv_bfloat16 h0 = __float2bfloat16(x.x), h1 = __float2bfloat16(x.y);
        __nv_bfloat16 h2 = __float2bfloat16(x.z), h3 = __float2bfloat16(x.w);
        __nv_bfloat16 l0 = __float2bfloat16(x.x - __bfloat162float(h0));
        __nv_bfloat16 l1 = __float2bfloat16(x.y - __bfloat162float(h1));
        __nv_bfloat16 l2 = __float2bfloat16(x.z - __bfloat162float(h2));
        __nv_bfloat16 l3 = __float2bfloat16(x.w - __bfloat162float(h3));
        __nv_bfloat162* ph = (__nv_bfloat162*)(sm + SO_AH + (row * SP + pos) * 2);
        __nv_bfloat162* pl = (__nv_bfloat162*)(sm + SO_AL + (row * SP + pos) * 2);
        ph[0] = __nv_bfloat162(h0, h1); ph[1] = __nv_bfloat162(h2, h3);
        pl[0] = __nv_bfloat162(l0, l1); pl[1] = __nv_bfloat162(l2, l3);
    }
}

// Warp GEMM via ldmatrix: 32x64 tile at (rb, cb).
// c element (mf,nf,e): row = rb+mf*16+lq+(e&2?8:0), col = cb+nf*8+lr*2+(e&1).
__device__ __forceinline__ void gemm_warp(uint32_t sb, int rb, int cb,
                                          int lane, float c[2][8][4]) {
    #pragma unroll
    for (int mf = 0; mf < 2; ++mf)
        #pragma unroll
        for (int nf = 0; nf < 8; ++nf)
            #pragma unroll
            for (int e = 0; e < 4; ++e) c[mf][nf][e] = 0.f;

    // A addresses: m = lane&15, k-half = (lane>>4)&1
    uint32_t a0 = sb + SO_AH +
        (uint32_t)(((rb + (lane & 15)) * SP + ((lane >> 4) & 1) * 8) * 2);
    uint32_t a1 = a0 + 16 * SP * 2;
    // B addresses: n = (lane&7) + ((lane&16)?8:0), k-half = (lane&8)?1:0
    uint32_t b0 = sb + SO_BH +
        (uint32_t)(((cb + (lane & 7) + ((lane & 16) ? 8 : 0)) * SP +
                    ((lane & 8) ? 8 : 0)) * 2);

    #pragma unroll 2
    for (int ks = 0; ks < 8; ++ks) {
        uint32_t ah0[4], ah1[4], al0[4], al1[4];
        LDSM4(ah0, a0); LDSM4(ah1, a1);
        LDSM4(al0, a0 + DAL); LDSM4(al1, a1 + DAL);
        #pragma unroll
        for (int p = 0; p < 4; ++p) {
            uint32_t bh[4], bl[4];
            uint32_t ba = b0 + (uint32_t)(p * 16 * SP * 2);
            LDSM4(bh, ba); LDSM4(bl, ba + DBL);
            // nf = 2p uses (bh[0],bh[1]) / (bl[0],bl[1])
            mma16816(c[0][2 * p], ah0, bh[0], bh[1]);
            mma16816(c[0][2 * p], ah0, bl[0], bl[1]);
            mma16816(c[0][2 * p], al0, bh[0], bh[1]);
            mma16816(c[1][2 * p], ah1, bh[0], bh[1]);
            mma16816(c[1][2 * p], ah1, bl[0], bl[1]);
            mma16816(c[1][2 * p], al1, bh[0], bh[1]);
            // nf = 2p+1 uses (bh[2],bh[3]) / (bl[2],bl[3])
            mma16816(c[0][2 * p + 1], ah0, bh[2], bh[3]);
            mma16816(c[0][2 * p + 1], ah0, bl[2], bl[3]);
            mma16816(c[0][2 * p + 1], al0, bh[2], bh[3]);
            mma16816(c[1][2 * p + 1], ah1, bh[2], bh[3]);
            mma16816(c[1][2 * p + 1], ah1, bl[2], bl[3]);
            mma16816(c[1][2 * p + 1], al1, bh[2], bh[3]);
        }
        a0 += 32; a1 += 32; b0 += 32;
    }
}

// ---------------- kernels ----------------
extern "C" __global__ void spooky_prep(const float* __restrict__ omega) {
    int n = blockIdx.x, k = threadIdx.x;
    float v = omega[k * MD + n] * 0.29730177875068026f;   // fold d^-1/4 into B
    __nv_bfloat16 hi = __float2bfloat16(v);
    __nv_bfloat16 lo = __float2bfloat16(v - __bfloat162float(hi));
    g_BT_hi[n * KD + k] = hi;
    g_BT_lo[n * KD + k] = lo;
    if (n == 0 && k == 0) { g_gmax_enc = 0u; g_ctrK = 0; g_ctrQ = 0; }
}

extern "C" __global__ void __launch_bounds__(NTH, 1)
spooky_kpass(const float* __restrict__ Kin, int ntot, int nbt) {
    extern __shared__ __align__(16) char sm[];
    const uint32_t sb = smem_u32(sm);
    float* s_h  = (float*)(sm + SO_H);
    float* redC = (float*)(sm + SO_RED);
    float* redR = (float*)(sm + SO_RR);
    int*   s_nt = (int*)(sm + SO_CT);
    const int tid = threadIdx.x, wid = tid >> 5, lane = tid & 31;
    const int lq = lane >> 2, lr = lane & 3;
    const int wr = wid & 3, wc = wid >> 2;
    const int rb = wr * 32, cb = wc * 64;

    if (tid == 0) s_nt[0] = atomicAdd(&g_ctrK, 1);
    __syncthreads();
    int rt = s_nt[0];
    if (rt >= nbt) return;

    load_B(sm, tid);
    load_A(Kin, rt * TM, sm, s_h, tid);
    __syncthreads();

    while (true) {
        const int base = rt * TM;
        float c[2][8][4];
        gemm_warp(sb, rb, cb, lane, c);

        float h4[4];
        #pragma unroll
        for (int s = 0; s < 4; ++s)
            h4[s] = s_h[rb + (s >> 1) * 16 + lq + (s & 1) * 8];

        float umax = -3.402823466e38f;
        #pragma unroll
        for (int mf = 0; mf < 2; ++mf)
            #pragma unroll
            for (int nf = 0; nf < 8; ++nf)
                #pragma unroll
                for (int e = 0; e < 4; ++e) umax = fmaxf(umax, c[mf][nf][e]);
        #pragma unroll
        for (int o = 16; o; o >>= 1)
            umax = fmaxf(umax, __shfl_xor_sync(0xffffffffu, umax, o));
        if (lane == 0) redR[wid] = umax;
        if (tid == 0) s_nt[0] = atomicAdd(&g_ctrK, 1);
        __syncthreads();

        float bmax = redR[0];
        #pragma unroll
        for (int w = 1; w < 16; ++w) bmax = fmaxf(bmax, redR[w]);
        const int nrt = s_nt[0];
        if (tid == 0) {
            g_bmax[rt] = bmax;
            atomicMax(&g_gmax_enc, enc_f(bmax));
        }
        if (nrt < nbt) load_A(Kin, nrt * TM, sm, s_h, tid);  // prefetch overlap

        // epilogue: exp(u-h-bmax) -> half scratch (col-major) + colsum partials
        float cs[16];
        #pragma unroll
        for (int j = 0; j < 16; ++j) cs[j] = 0.f;
        #pragma unroll
        for (int mf = 0; mf < 2; ++mf)
            #pragma unroll
            for (int nf = 0; nf < 8; ++nf)
                #pragma unroll
                for (int e = 0; e < 4; ++e) {
                    int rloc = rb + mf * 16 + lq + ((e & 2) ? 8 : 0);
                    int col  = cb + nf * 8 + lr * 2 + (e & 1);
                    float v = __expf(c[mf][nf][e] - h4[mf * 2 + ((e >> 1) & 1)] - bmax);
                    g_UKh[(size_t)col * ntot + (base + rloc)] = __float2half_rn(v);
                    cs[nf * 2 + (e & 1)] += v;
                }
        #pragma unroll
        for (int j = 0; j < 16; ++j) {
            float v = cs[j];
            v += __shfl_xor_sync(0xffffffffu, v, 4);
            v += __shfl_xor_sync(0xffffffffu, v, 8);
            v += __shfl_xor_sync(0xffffffffu, v, 16);
            cs[j] = v;
        }
        if (lq == 0) {
            #pragma unroll
            for (int nf = 0; nf < 8; ++nf)
                #pragma unroll
                for (int e1 = 0; e1 < 2; ++e1)
                    redC[(cb + nf * 8 + lr * 2 + e1) * 4 + wr] = cs[nf * 2 + e1];
        }
        __syncthreads();
        if (tid < MD)
            g_Spart[rt * MD + tid] = redC[tid * 4] + redC[tid * 4 + 1] +
                                     redC[tid * 4 + 2] + redC[tid * 4 + 3];
        __syncthreads();
        if (nrt >= nbt) break;
        rt = nrt;
    }
}

extern "C" __global__ void spooky_fin(int nbt, int ntot) {
    __shared__ float red[256];
    const int j = blockIdx.x, tid = threadIdx.x;
    const float g = dec_f(g_gmax_enc);
    float a = 0.f;
    for (int r = tid; r < nbt; r += 256)
        a += g_Spart[r * MD + j] * __expf(g_bmax[r] - g);
    red[tid] = a;
    __syncthreads();
    for (int s = 128; s; s >>= 1) {
        if (tid < s) red[tid] += red[tid + s];
        __syncthreads();
    }
    if (tid == 0) {
        g_S[j] = (red[0] + (float)ntot * 1e-4f) * 0.0625f;
        if (j == 0) g_gmax = g;
    }
}

extern "C" __global__ void __launch_bounds__(NTH, 1)
spooky_qpass(const float* __restrict__ Q, const float* __restrict__ V,
             float* __restrict__ out, int ntot, int nbt) {
    extern __shared__ __align__(16) char sm[];
    const uint32_t sb = smem_u32(sm);
    float* s_h  = (float*)(sm + SO_H);
    float* s_S  = (float*)(sm + SO_S);
    float* redM = (float*)(sm + SO_RED);
    float* redW = (float*)(sm + SO_RED + 2048);
    float* redN = (float*)(sm + SO_RED + 4096);
    float* s_sc = (float*)(sm + SO_SC);
    int*   s_nt = (int*)(sm + SO_CT);
    const int tid = threadIdx.x, wid = tid >> 5, lane = tid & 31;
    const int lq = lane >> 2, lr = lane & 3;
    const int wr = wid & 3, wc = wid >> 2;
    const int rb = wr * 32, cb = wc * 64;

    if (tid == 0) s_nt[0] = atomicAdd(&g_ctrQ, 1);
    __syncthreads();
    int rt = s_nt[0];
    if (rt >= nbt) return;

    if (tid < MD) s_S[tid] = g_S[tid];
    load_B(sm, tid);
    load_A(Q, rt * TM, sm, s_h, tid);
    __syncthreads();

    const float gmx = g_gmax;

    while (true) {
        const int base = rt * TM;
        float c[2][8][4];
        gemm_warp(sb, rb, cb, lane, c);

        float h4[4];
        #pragma unroll
        for (int s = 0; s < 4; ++s)
            h4[s] = s_h[rb + (s >> 1) * 16 + lq + (s & 1) * 8];

        // round 1: per-row max (warp-local cols, then cross-warp via smem)
        #pragma unroll
        for (int s = 0; s < 4; ++s) {
            int mf = s >> 1, hi = s & 1;
            float m = c[mf][0][hi * 2];
            #pragma unroll
            for (int nf = 0; nf < 8; ++nf) {
                m = fmaxf(m, c[mf][nf][hi * 2]);
                m = fmaxf(m, c[mf][nf][hi * 2 + 1]);
            }
            m = fmaxf(m, __shfl_xor_sync(0xffffffffu, m, 1));
            m = fmaxf(m, __shfl_xor_sync(0xffffffffu, m, 2));
            if (lr == 0) redM[(rb + mf * 16 + lq + hi * 8) * 4 + wc] = m;
        }
        if (tid == 0) s_nt[0] = atomicAdd(&g_ctrQ, 1);
        __syncthreads();

        float hb4[4];
        #pragma unroll
        for (int s = 0; s < 4; ++s) {
            int rloc = rb + (s >> 1) * 16 + lq + (s & 1) * 8;
            float rm = fmaxf(fmaxf(redM[rloc * 4], redM[rloc * 4 + 1]),
                             fmaxf(redM[rloc * 4 + 2], redM[rloc * 4 + 3]));
            hb4[s] = h4[s] + rm;
        }
        const int nrt = s_nt[0];
        const float ebm = __expf(g_bmax[rt] - gmx);
        if (nrt < nbt) load_A(Q, nrt * TM, sm, s_h, tid);   // prefetch overlap

        // round 2: w and norm partials
        #pragma unroll
        for (int s = 0; s < 4; ++s) {
            int mf = s >> 1, hi = s & 1;
            int rloc = rb + mf * 16 + lq + hi * 8;
            int rowg = base + rloc;
            float hb = hb4[s];
            float wa = 0.f, na = 0.f;
            #pragma unroll
            for (int nf = 0; nf < 8; ++nf)
                #pragma unroll
                for (int e1 = 0; e1 < 2; ++e1) {
                    int col = cb + nf * 8 + lr * 2 + e1;
                    float qp = __expf(c[mf][nf][hi * 2 + e1] - hb) + 1e-4f;
                    float kp = __half2float(g_UKh[(size_t)col * ntot + rowg]) * ebm + 1e-4f;
                    wa += qp * kp;
                    na += qp * s_S[col];
                }
            wa += __shfl_xor_sync(0xffffffffu, wa, 1);
            wa += __shfl_xor_sync(0xffffffffu, wa, 2);
            na += __shfl_xor_sync(0xffffffffu, na, 1);
            na += __shfl_xor_sync(0xffffffffu, na, 2);
            if (lr == 0) { redW[rloc * 4 + wc] = wa; redN[rloc * 4 + wc] = na; }
        }
        __syncthreads();

        if (tid < TM) {
            float w = redW[tid * 4] + redW[tid * 4 + 1] + redW[tid * 4 + 2] + redW[tid * 4 + 3];
            float n = redN[tid * 4] + redN[tid * 4 + 1] + redN[tid * 4 + 2] + redN[tid * 4 + 3];
            s_sc[tid] = (w * (1.f / 256.f)) / (n * (1.f / 16.f) + 1e-8f);
        }
        __syncthreads();

        #pragma unroll
        for (int it = 0; it < 8; ++it) {
            int r = wid * 8 + it;
            float scv = s_sc[r];
            size_t o = (size_t)(base + r) * KD + lane * 4;
            float4 v = *(const float4*)(V + o);
            v.x *= scv; v.y *= scv; v.z *= scv; v.w *= scv;
            *(float4*)(out + o) = v;
        }
        __syncthreads();
        if (nrt >= nbt) break;
        rt = nrt;
    }
}

// ---------------- launcher ----------------
extern "C" void kernel_launch(void* const* d_in, const int* in_sizes, int n_in,
                              void* d_out, int out_size) {
    const float* Q     = (const float*)d_in[0];
    const float* K     = (const float*)d_in[1];
    const float* V     = (const float*)d_in[2];
    const float* omega = (const float*)d_in[3];
    const int n  = in_sizes[0] / KD;
    const int nb = n / TM;

    cudaFuncSetAttribute(spooky_kpass, cudaFuncAttributeMaxDynamicSharedMemorySize, SMEM_BYTES);
    cudaFuncSetAttribute(spooky_qpass, cudaFuncAttributeMaxDynamicSharedMemorySize, SMEM_BYTES);

    spooky_prep<<<MD, KD>>>(omega);
    spooky_kpass<<<PGRID, NTH, SMEM_BYTES>>>(K, n, nb);
    spooky_fin<<<MD, 256>>>(nb, n);
    spooky_qpass<<<PGRID, NTH, SMEM_BYTES>>>(Q, V, (float*)d_out, n, nb);
}

// round 12
// speedup vs baseline: 2.4174x; 1.1097x over previous
#include <cuda_runtime.h>
#include <cuda_bf16.h>
#include <cuda_fp16.h>
#include <cstdint>

// ---------------------------------------------------------------------------
// SpookyNetAttention — split-bf16 (hi/lo, 3-product) GEMM on mma.sync,
// ldmatrix fragments, persistent CTAs + prefetch, and FRAGMENT-ORDER fp16
// scratch: kpass/qpass share the same tile/warp/lane mapping, so scratch is
// stored in register order -> 8x STG.128 / LDG.128 per thread per tile.
//
//   kpass: U_K -> exp(Uk-h-bmax) (half, fragment order), colsum partials,
//          per-tile bmax, global gmax via encoded atomicMax
//   fin:   S[j] = (sum_t e^{bmax_t-gmax}*Spart[t][j] + N*1e-4)/16
//   qpass: U_Q -> rowmax, Qp, reload scratch (*e^{bmax-gmax}), w/norm,
//          out = V * w/norm
// ---------------------------------------------------------------------------

#define KD   128
#define MD   256
#define TM   128
#define NTH  512            // 16 warps, 4x4 warp grid, warp tile 32x64
#define N_MAX 262144
#define MAX_NB (N_MAX / TM)
#define SP   136            // padded bf16 row stride; word stride 68 = 4 mod 32
#define PGRID 152           // persistent CTAs (GB300: 152 SMs)

// smem byte offsets
#define SO_BH   0                       // [256][136] bf16
#define SO_BL   69632
#define SO_AH   139264                  // [128][136] bf16
#define SO_AL   174080
#define SO_H    208896                  // 128 floats
#define SO_S    209408                  // 256 floats
#define SO_RED  210432                  // 3 x 2KB reduction buffers
#define SO_SC   216576                  // 128 floats
#define SO_RR   217088                  // 16 floats (warp maxes)
#define SO_CT   217152                  // next-tile broadcast (int)
#define SMEM_BYTES 217216

#define DAL (SO_AL - SO_AH)
#define DBL (SO_BL - SO_BH)

// device scratch (allocation-free per harness rules)
__device__ __nv_bfloat16 g_BT_hi[MD * KD];
__device__ __nv_bfloat16 g_BT_lo[MD * KD];
__device__ uint4    g_UK4[(size_t)N_MAX * MD / 8];  // exp(Uk-h-bmax), half,
                                                    // fragment order
__device__ float    g_Spart[MAX_NB * MD];
__device__ float    g_bmax[MAX_NB];
__device__ float    g_S[MD];
__device__ unsigned g_gmax_enc;
__device__ float    g_gmax;
__device__ int      g_ctrK, g_ctrQ;

// ---------------- helpers ----------------
__device__ __forceinline__ unsigned enc_f(float f) {
    unsigned u = __float_as_uint(f);
    return (u & 0x80000000u) ? ~u : (u | 0x80000000u);
}
__device__ __forceinline__ float dec_f(unsigned u) {
    u = (u & 0x80000000u) ? (u & 0x7FFFFFFFu) : ~u;
    return __uint_as_float(u);
}
__device__ __forceinline__ uint32_t smem_u32(const void* p) {
    uint32_t a;
    asm("{ .reg .u64 t; cvta.to.shared.u64 t, %1; cvt.u32.u64 %0, t; }" : "=r"(a) : "l"(p));
    return a;
}
__device__ __forceinline__ void mma16816(float c[4], const uint32_t a[4],
                                         uint32_t b0, uint32_t b1) {
    asm volatile(
        "mma.sync.aligned.m16n8k16.row.col.f32.bf16.bf16.f32 "
        "{%0,%1,%2,%3}, {%4,%5,%6,%7}, {%8,%9}, {%0,%1,%2,%3};"
        : "+f"(c[0]), "+f"(c[1]), "+f"(c[2]), "+f"(c[3])
        : "r"(a[0]), "r"(a[1]), "r"(a[2]), "r"(a[3]), "r"(b0), "r"(b1));
}
#define LDSM4(R, A)                                                         \
    asm volatile("ldmatrix.sync.aligned.m8n8.x4.shared.b16 {%0,%1,%2,%3}, [%4];" \
        : "=r"((R)[0]), "=r"((R)[1]), "=r"((R)[2]), "=r"((R)[3]) : "r"(A))

__device__ __forceinline__ uint32_t pack_h2(float a, float b) {
    __half2 h = __floats2half2_rn(a, b);
    return *(uint32_t*)&h;
}

// ---------------- shared device functions ----------------

// B (omega^T hi/lo) -> padded smem. 512 threads, once per CTA.
__device__ __forceinline__ void load_B(char* sm, int tid) {
    #pragma unroll
    for (int it = 0; it < 16; ++it) {
        int c = tid + it * NTH;
        int row = c >> 5;
        int pos = (c & 31) * 4;
        uint2 vh = *(const uint2*)((const char*)g_BT_hi + (row * KD + pos) * 2);
        uint2 vl = *(const uint2*)((const char*)g_BT_lo + (row * KD + pos) * 2);
        *(uint2*)(sm + SO_BH + (row * SP + pos) * 2) = vh;
        *(uint2*)(sm + SO_BL + (row * SP + pos) * 2) = vl;
    }
}

// A tile: 128 rows fp32 -> bf16 hi/lo padded smem + per-row h.
__device__ __forceinline__ void load_A(const float* __restrict__ X, int base,
                                       char* sm, float* s_h, int tid) {
    const int lane = tid & 31;
    #pragma unroll
    for (int it = 0; it < 8; ++it) {
        int c = tid + it * NTH;
        int row = c >> 5;
        int pos = (c & 31) * 4;
        float4 x = *(const float4*)(X + (size_t)(base + row) * KD + pos);
        float ss = x.x * x.x + x.y * x.y + x.z * x.z + x.w * x.w;
        #pragma unroll
        for (int o = 16; o; o >>= 1) ss += __shfl_xor_sync(0xffffffffu, ss, o);
        if (lane == 0) s_h[row] = ss * 0.04419417382415922f;  // 1/(2*sqrt(128))

        __nv_bfloat16 h0 = __float2bfloat16(x.x), h1 = __float2bfloat16(x.y);
        __nv_bfloat16 h2 = __float2bfloat16(x.z), h3 = __float2bfloat16(x.w);
        __nv_bfloat16 l0 = __float2bfloat16(x.x - __bfloat162float(h0));
        __nv_bfloat16 l1 = __float2bfloat16(x.y - __bfloat162float(h1));
        __nv_bfloat16 l2 = __float2bfloat16(x.z - __bfloat162float(h2));
        __nv_bfloat16 l3 = __float2bfloat16(x.w - __bfloat162float(h3));
        __nv_bfloat162* ph = (__nv_bfloat162*)(sm + SO_AH + (row * SP + pos) * 2);
        __nv_bfloat162* pl = (__nv_bfloat162*)(sm + SO_AL + (row * SP + pos) * 2);
        ph[0] = __nv_bfloat162(h0, h1); ph[1] = __nv_bfloat162(h2, h3);
        pl[0] = __nv_bfloat162(l0, l1); pl[1] = __nv_bfloat162(l2, l3);
    }
}

// Warp GEMM via ldmatrix: 32x64 tile at (rb, cb).
// c element (mf,nf,e): row = rb+mf*16+lq+(e&2?8:0), col = cb+nf*8+lr*2+(e&1).
__device__ __forceinline__ void gemm_warp(uint32_t sb, int rb, int cb,
                                          int lane, float c[2][8][4]) {
    #pragma unroll
    for (int mf = 0; mf < 2; ++mf)
        #pragma unroll
        for (int nf = 0; nf < 8; ++nf)
            #pragma unroll
            for (int e = 0; e < 4; ++e) c[mf][nf][e] = 0.f;

    uint32_t a0 = sb + SO_AH +
        (uint32_t)(((rb + (lane & 15)) * SP + ((lane >> 4) & 1) * 8) * 2);
    uint32_t a1 = a0 + 16 * SP * 2;
    uint32_t b0 = sb + SO_BH +
        (uint32_t)(((cb + (lane & 7) + ((lane & 16) ? 8 : 0)) * SP +
                    ((lane & 8) ? 8 : 0)) * 2);

    #pragma unroll 2
    for (int ks = 0; ks < 8; ++ks) {
        uint32_t ah0[4], ah1[4], al0[4], al1[4];
        LDSM4(ah0, a0); LDSM4(ah1, a1);
        LDSM4(al0, a0 + DAL); LDSM4(al1, a1 + DAL);
        #pragma unroll
        for (int p = 0; p < 4; ++p) {
            uint32_t bh[4], bl[4];
            uint32_t ba = b0 + (uint32_t)(p * 16 * SP * 2);
            LDSM4(bh, ba); LDSM4(bl, ba + DBL);
            mma16816(c[0][2 * p], ah0, bh[0], bh[1]);
            mma16816(c[0][2 * p], ah0, bl[0], bl[1]);
            mma16816(c[0][2 * p], al0, bh[0], bh[1]);
            mma16816(c[1][2 * p], ah1, bh[0], bh[1]);
            mma16816(c[1][2 * p], ah1, bl[0], bl[1]);
            mma16816(c[1][2 * p], al1, bh[0], bh[1]);
            mma16816(c[0][2 * p + 1], ah0, bh[2], bh[3]);
            mma16816(c[0][2 * p + 1], ah0, bl[2], bl[3]);
            mma16816(c[0][2 * p + 1], al0, bh[2], bh[3]);
            mma16816(c[1][2 * p + 1], ah1, bh[2], bh[3]);
            mma16816(c[1][2 * p + 1], ah1, bl[2], bl[3]);
            mma16816(c[1][2 * p + 1], al1, bh[2], bh[3]);
        }
        a0 += 32; a1 += 32; b0 += 32;
    }
}

// ---------------- kernels ----------------
extern "C" __global__ void spooky_prep(const float* __restrict__ omega) {
    int n = blockIdx.x, k = threadIdx.x;
    float v = omega[k * MD + n] * 0.29730177875068026f;   // fold d^-1/4 into B
    __nv_bfloat16 hi = __float2bfloat16(v);
    __nv_bfloat16 lo = __float2bfloat16(v - __bfloat162float(hi));
    g_BT_hi[n * KD + k] = hi;
    g_BT_lo[n * KD + k] = lo;
    if (n == 0 && k == 0) { g_gmax_enc = 0u; g_ctrK = 0; g_ctrQ = 0; }
}

extern "C" __global__ void __launch_bounds__(NTH, 1)
spooky_kpass(const float* __restrict__ Kin, int ntot, int nbt) {
    extern __shared__ __align__(16) char sm[];
    const uint32_t sb = smem_u32(sm);
    float* s_h  = (float*)(sm + SO_H);
    float* redC = (float*)(sm + SO_RED);
    float* redR = (float*)(sm + SO_RR);
    int*   s_nt = (int*)(sm + SO_CT);
    const int tid = threadIdx.x, wid = tid >> 5, lane = tid & 31;
    const int lq = lane >> 2, lr = lane & 3;
    const int wr = wid & 3, wc = wid >> 2;
    const int rb = wr * 32, cb = wc * 64;

    if (tid == 0) s_nt[0] = atomicAdd(&g_ctrK, 1);
    __syncthreads();
    int rt = s_nt[0];
    if (rt >= nbt) return;

    load_B(sm, tid);
    load_A(Kin, rt * TM, sm, s_h, tid);
    __syncthreads();

    while (true) {
        float c[2][8][4];
        gemm_warp(sb, rb, cb, lane, c);

        float h4[4];
        #pragma unroll
        for (int s = 0; s < 4; ++s)
            h4[s] = s_h[rb + (s >> 1) * 16 + lq + (s & 1) * 8];

        float umax = -3.402823466e38f;
        #pragma unroll
        for (int mf = 0; mf < 2; ++mf)
            #pragma unroll
            for (int nf = 0; nf < 8; ++nf)
                #pragma unroll
                for (int e = 0; e < 4; ++e) umax = fmaxf(umax, c[mf][nf][e]);
        #pragma unroll
        for (int o = 16; o; o >>= 1)
            umax = fmaxf(umax, __shfl_xor_sync(0xffffffffu, umax, o));
        if (lane == 0) redR[wid] = umax;
        if (tid == 0) s_nt[0] = atomicAdd(&g_ctrK, 1);
        __syncthreads();

        float bmax = redR[0];
        #pragma unroll
        for (int w = 1; w < 16; ++w) bmax = fmaxf(bmax, redR[w]);
        const int nrt = s_nt[0];
        if (tid == 0) {
            g_bmax[rt] = bmax;
            atomicMax(&g_gmax_enc, enc_f(bmax));
        }
        if (nrt < nbt) load_A(Kin, nrt * TM, sm, s_h, tid);  // prefetch overlap

        // epilogue: exp(u-h-bmax) -> half scratch in FRAGMENT ORDER
        float cs[16];
        #pragma unroll
        for (int j = 0; j < 16; ++j) cs[j] = 0.f;
        uint32_t pk[32];
        #pragma unroll
        for (int mf = 0; mf < 2; ++mf)
            #pragma unroll
            for (int nf = 0; nf < 8; ++nf) {
                float v0 = __expf(c[mf][nf][0] - h4[mf * 2] - bmax);
                float v1 = __expf(c[mf][nf][1] - h4[mf * 2] - bmax);
                float v2 = __expf(c[mf][nf][2] - h4[mf * 2 + 1] - bmax);
                float v3 = __expf(c[mf][nf][3] - h4[mf * 2 + 1] - bmax);
                cs[nf * 2 + 0] += v0 + v2;
                cs[nf * 2 + 1] += v1 + v3;
                pk[(mf * 8 + nf) * 2 + 0] = pack_h2(v0, v1);
                pk[(mf * 8 + nf) * 2 + 1] = pack_h2(v2, v3);
            }
        {
            uint4* dst = g_UK4 + ((size_t)rt * 16 + wid) * 256 + lane * 8;
            #pragma unroll
            for (int q = 0; q < 8; ++q)
                dst[q] = make_uint4(pk[4 * q], pk[4 * q + 1], pk[4 * q + 2], pk[4 * q + 3]);
        }
        #pragma unroll
        for (int j = 0; j < 16; ++j) {
            float v = cs[j];
            v += __shfl_xor_sync(0xffffffffu, v, 4);
            v += __shfl_xor_sync(0xffffffffu, v, 8);
            v += __shfl_xor_sync(0xffffffffu, v, 16);
            cs[j] = v;
        }
        if (lq == 0) {
            #pragma unroll
            for (int nf = 0; nf < 8; ++nf)
                #pragma unroll
                for (int e1 = 0; e1 < 2; ++e1)
                    redC[(cb + nf * 8 + lr * 2 + e1) * 4 + wr] = cs[nf * 2 + e1];
        }
        __syncthreads();
        if (tid < MD)
            g_Spart[rt * MD + tid] = redC[tid * 4] + redC[tid * 4 + 1] +
                                     redC[tid * 4 + 2] + redC[tid * 4 + 3];
        __syncthreads();
        if (nrt >= nbt) break;
        rt = nrt;
    }
}

extern "C" __global__ void spooky_fin(int nbt, int ntot) {
    __shared__ float red[256];
    const int j = blockIdx.x, tid = threadIdx.x;
    const float g = dec_f(g_gmax_enc);
    float a = 0.f;
    for (int r = tid; r < nbt; r += 256)
        a += g_Spart[r * MD + j] * __expf(g_bmax[r] - g);
    red[tid] = a;
    __syncthreads();
    for (int s = 128; s; s >>= 1) {
        if (tid < s) red[tid] += red[tid + s];
        __syncthreads();
    }
    if (tid == 0) {
        g_S[j] = (red[0] + (float)ntot * 1e-4f) * 0.0625f;
        if (j == 0) g_gmax = g;
    }
}

extern "C" __global__ void __launch_bounds__(NTH, 1)
spooky_qpass(const float* __restrict__ Q, const float* __restrict__ V,
             float* __restrict__ out, int ntot, int nbt) {
    extern __shared__ __align__(16) char sm[];
    const uint32_t sb = smem_u32(sm);
    float* s_h  = (float*)(sm + SO_H);
    float* s_S  = (float*)(sm + SO_S);
    float* redM = (float*)(sm + SO_RED);
    float* redW = (float*)(sm + SO_RED + 2048);
    float* redN = (float*)(sm + SO_RED + 4096);
    float* s_sc = (float*)(sm + SO_SC);
    int*   s_nt = (int*)(sm + SO_CT);
    const int tid = threadIdx.x, wid = tid >> 5, lane = tid & 31;
    const int lq = lane >> 2, lr = lane & 3;
    const int wr = wid & 3, wc = wid >> 2;
    const int rb = wr * 32, cb = wc * 64;

    if (tid == 0) s_nt[0] = atomicAdd(&g_ctrQ, 1);
    __syncthreads();
    int rt = s_nt[0];
    if (rt >= nbt) return;

    if (tid < MD) s_S[tid] = g_S[tid];
    load_B(sm, tid);
    load_A(Q, rt * TM, sm, s_h, tid);
    __syncthreads();

    const float gmx = g_gmax;

    while (true) {
        const int base = rt * TM;
        float c[2][8][4];
        gemm_warp(sb, rb, cb, lane, c);

        float h4[4];
        #pragma unroll
        for (int s = 0; s < 4; ++s)
            h4[s] = s_h[rb + (s >> 1) * 16 + lq + (s & 1) * 8];

        // round 1: per-row max (warp-local cols, then cross-warp via smem)
        #pragma unroll
        for (int s = 0; s < 4; ++s) {
            int mf = s >> 1, hi = s & 1;
            float m = c[mf][0][hi * 2];
            #pragma unroll
            for (int nf = 0; nf < 8; ++nf) {
                m = fmaxf(m, c[mf][nf][hi * 2]);
                m = fmaxf(m, c[mf][nf][hi * 2 + 1]);
            }
            m = fmaxf(m, __shfl_xor_sync(0xffffffffu, m, 1));
            m = fmaxf(m, __shfl_xor_sync(0xffffffffu, m, 2));
            if (lr == 0) redM[(rb + mf * 16 + lq + hi * 8) * 4 + wc] = m;
        }
        if (tid == 0) s_nt[0] = atomicAdd(&g_ctrQ, 1);

        // kp scratch reload (fragment order, coalesced 128B) — issue early
        uint32_t pk[32];
        {
            const uint4* src = g_UK4 + ((size_t)rt * 16 + wid) * 256 + lane * 8;
            #pragma unroll
            for (int q = 0; q < 8; ++q) {
                uint4 t = src[q];
                pk[4 * q] = t.x; pk[4 * q + 1] = t.y;
                pk[4 * q + 2] = t.z; pk[4 * q + 3] = t.w;
            }
        }
        __syncthreads();

        float hb4[4];
        #pragma unroll
        for (int s = 0; s < 4; ++s) {
            int rloc = rb + (s >> 1) * 16 + lq + (s & 1) * 8;
            float rm = fmaxf(fmaxf(redM[rloc * 4], redM[rloc * 4 + 1]),
                             fmaxf(redM[rloc * 4 + 2], redM[rloc * 4 + 3]));
            hb4[s] = h4[s] + rm;
        }
        const int nrt = s_nt[0];
        const float ebm = __expf(g_bmax[rt] - gmx);
        if (nrt < nbt) load_A(Q, nrt * TM, sm, s_h, tid);   // prefetch overlap

        // round 2: w and norm partials
        #pragma unroll
        for (int s = 0; s < 4; ++s) {
            int mf = s >> 1, hi = s & 1;
            int rloc = rb + mf * 16 + lq + hi * 8;
            float hb = hb4[s];
            float wa = 0.f, na = 0.f;
            #pragma unroll
            for (int nf = 0; nf < 8; ++nf) {
                __half2 hh = *(__half2*)&pk[(mf * 8 + nf) * 2 + hi];
                float2 kf = __half22float2(hh);
                #pragma unroll
                for (int e1 = 0; e1 < 2; ++e1) {
                    int col = cb + nf * 8 + lr * 2 + e1;
                    float qp = __expf(c[mf][nf][hi * 2 + e1] - hb) + 1e-4f;
                    float kp = (e1 ? kf.y : kf.x) * ebm + 1e-4f;
                    wa += qp * kp;
                    na += qp * s_S[col];
                }
            }
            wa += __shfl_xor_sync(0xffffffffu, wa, 1);
            wa += __shfl_xor_sync(0xffffffffu, wa, 2);
            na += __shfl_xor_sync(0xffffffffu, na, 1);
            na += __shfl_xor_sync(0xffffffffu, na, 2);
            if (lr == 0) { redW[rloc * 4 + wc] = wa; redN[rloc * 4 + wc] = na; }
        }
        __syncthreads();

        if (tid < TM) {
            float w = redW[tid * 4] + redW[tid * 4 + 1] + redW[tid * 4 + 2] + redW[tid * 4 + 3];
            float n = redN[tid * 4] + redN[tid * 4 + 1] + redN[tid * 4 + 2] + redN[tid * 4 + 3];
            s_sc[tid] = (w * (1.f / 256.f)) / (n * (1.f / 16.f) + 1e-8f);
        }
        __syncthreads();

        #pragma unroll
        for (int it = 0; it < 8; ++it) {
            int r = wid * 8 + it;
            float scv = s_sc[r];
            size_t o = (size_t)(base + r) * KD + lane * 4;
            float4 v = *(const float4*)(V + o);
            v.x *= scv; v.y *= scv; v.z *= scv; v.w *= scv;
            *(float4*)(out + o) = v;
        }
        __syncthreads();
        if (nrt >= nbt) break;
        rt = nrt;
    }
}

// ---------------- launcher ----------------
extern "C" void kernel_launch(void* const* d_in, const int* in_sizes, int n_in,
                              void* d_out, int out_size) {
    const float* Q     = (const float*)d_in[0];
    const float* K     = (const float*)d_in[1];
    const float* V     = (const float*)d_in[2];
    const float* omega = (const float*)d_in[3];
    const int n  = in_sizes[0] / KD;
    const int nb = n / TM;

    cudaFuncSetAttribute(spooky_kpass, cudaFuncAttributeMaxDynamicSharedMemorySize, SMEM_BYTES);
    cudaFuncSetAttribute(spooky_qpass, cudaFuncAttributeMaxDynamicSharedMemorySize, SMEM_BYTES);

    spooky_prep<<<MD, KD>>>(omega);
    spooky_kpass<<<PGRID, NTH, SMEM_BYTES>>>(K, n, nb);
    spooky_fin<<<MD, 256>>>(nb, n);
    spooky_qpass<<<PGRID, NTH, SMEM_BYTES>>>(Q, V, (float*)d_out, n, nb);
}